// round 11
// baseline (speedup 1.0000x reference)
#include <cuda_runtime.h>
#include <cuda_bf16.h>

typedef unsigned int u32;
typedef unsigned long long u64;

#define TPB 128
#define QPB 2
#define GRID 444   // 148 SMs x 3 CTAs

// ---- dynamic SMEM layout (bytes) ----
#define O_W1H 0
#define O_W1L 5120
#define O_W2H 10240
#define O_W2L 19456
#define O_W3H 28672
#define O_W3L 33280
#define O_X   37888
#define O_APOS 56320
#define O_LIST 62464
#define O_SS  66560
#define O_AFEAT 67072
#define DYN_SMEM 71168

#define S1 80
#define S2 144
#define SX 144

__device__ int g_work_counter;

__global__ void reset_counter_kernel() { g_work_counter = 0; }

__device__ __forceinline__ u32 bpack(float v0, float v1) {
    u32 r;
    asm("cvt.rn.satfinite.bf16x2.f32 %0, %1, %2;" : "=r"(r) : "f"(v1), "f"(v0));
    return r;
}
__device__ __forceinline__ void split2(float v0, float v1, u32& hi, u32& lo) {
    const u32 ch = bpack(v0, v1);
    const float h0 = __uint_as_float(ch << 16);
    const float h1 = __uint_as_float(ch & 0xffff0000u);
    hi = ch;
    lo = bpack(v0 - h0, v1 - h1);
}
__device__ __forceinline__ void mma16816(float* d, const u32* a, u32 b0, u32 b1) {
    asm volatile(
        "mma.sync.aligned.m16n8k16.row.col.f32.bf16.bf16.f32 "
        "{%0,%1,%2,%3}, {%4,%5,%6,%7}, {%8,%9}, {%0,%1,%2,%3};"
        : "+f"(d[0]), "+f"(d[1]), "+f"(d[2]), "+f"(d[3])
        : "r"(a[0]), "r"(a[1]), "r"(a[2]), "r"(a[3]), "r"(b0), "r"(b1));
}

__global__ __launch_bounds__(TPB, 3)
void fieldnet_mma_kernel(
    const float* __restrict__ apos, const float* __restrict__ afeat,
    const float* __restrict__ qpos,
    const float* __restrict__ W1, const float* __restrict__ b1,
    const float* __restrict__ W2, const float* __restrict__ b2,
    const float* __restrict__ W3, const float* __restrict__ b3,
    const float* __restrict__ W4, const float* __restrict__ b4,
    const float* __restrict__ W5, const float* __restrict__ b5,
    const float* __restrict__ W6, const float* __restrict__ b6,
    float* __restrict__ out, int NA, int NQ)
{
    extern __shared__ __align__(16) char sm[];
    __shared__ __align__(16) float sb1f[64], sb2f[64], sb3f[32], sW4f[32];
    __shared__ __align__(16) float sW5[192], sW6[193], sb5[64];
    __shared__ float sQ[QPB * 3], sRed[12], sWgt[3], sOut[6];
    __shared__ int sCnt[4], sOff[5];
    __shared__ int sGrp;

    const int tid = threadIdx.x;
    const int lane = tid & 31;
    const int wid = tid >> 5;
    const int g = lane >> 2;
    const int t = lane & 3;
    const unsigned lanemask_lt = (1u << lane) - 1u;

    float* sApos = (float*)(sm + O_APOS);
    float* sAfeat = (float*)(sm + O_AFEAT);
    unsigned short* sList = (unsigned short*)(sm + O_LIST);
    float* sSf = (float*)(sm + O_SS);

    // ================= one-time per-CTA prep =================
    {
        u32* p = (u32*)sm;
        for (int i = tid; i < O_X / 4; i += TPB) p[i] = 0;
    }
    __syncthreads();

    for (int i = tid; i < NA * 3; i += TPB) sApos[i] = apos[i];
    for (int i = tid; i < NA * 2; i += TPB) sAfeat[i] = afeat[i];
    for (int i = tid; i < 3 * 64; i += TPB) { sW5[i] = W5[i]; sW6[i] = W6[i]; }
    if (tid < 64) { sb1f[tid] = b1[tid]; sb2f[tid] = b2[tid]; sb5[tid] = b5[tid]; }
    if (tid < 32) { sb3f[tid] = b3[tid]; sW4f[tid] = W4[tid]; }

    for (int i = tid; i < 18 * 64; i += TPB) {
        int k = i >> 6, n = i & 63;
        float v = W1[i];
        __nv_bfloat16 hb = __float2bfloat16(v);
        __nv_bfloat16 lb = __float2bfloat16(v - __bfloat162float(hb));
        *(unsigned short*)(sm + O_W1H + n * S1 + k * 2) = *(unsigned short*)&hb;
        *(unsigned short*)(sm + O_W1L + n * S1 + k * 2) = *(unsigned short*)&lb;
    }
    for (int i = tid; i < 64 * 64; i += TPB) {
        int k = i >> 6, n = i & 63;
        float v = W2[i];
        __nv_bfloat16 hb = __float2bfloat16(v);
        __nv_bfloat16 lb = __float2bfloat16(v - __bfloat162float(hb));
        *(unsigned short*)(sm + O_W2H + n * S2 + k * 2) = *(unsigned short*)&hb;
        *(unsigned short*)(sm + O_W2L + n * S2 + k * 2) = *(unsigned short*)&lb;
    }
    for (int i = tid; i < 64 * 32; i += TPB) {
        int k = i >> 5, n = i & 31;
        float v = W3[i];
        __nv_bfloat16 hb = __float2bfloat16(v);
        __nv_bfloat16 lb = __float2bfloat16(v - __bfloat162float(hb));
        *(unsigned short*)(sm + O_W3H + n * S2 + k * 2) = *(unsigned short*)&hb;
        *(unsigned short*)(sm + O_W3L + n * S2 + k * 2) = *(unsigned short*)&lb;
    }

    const float b4s = b4[0];
    const int ngroups = (NQ + QPB - 1) / QPB;
    const char* pX = sm + O_X;
    const int halfNA = NA >> 1;

    // ================= persistent work-stealing loop =================
    while (true) {
        __syncthreads();   // protect sGrp / buffers from previous group
        if (tid == 0) sGrp = atomicAdd(&g_work_counter, 1);
        __syncthreads();
        const int grp = sGrp;
        if (grp >= ngroups) break;

        if (tid < QPB * 3) {
            int qg = grp * QPB + tid / 3;
            sQ[tid] = (qg < NQ) ? qpos[qg * 3 + (tid % 3)] : 1e30f;
        }
        __syncthreads();

        // ---- Phase A: culling + compaction (2 warps per query) ----
        const int qw = wid >> 1;            // query slot 0/1
        const int aBeg = (wid & 1) * halfNA;
        const int aEnd = aBeg + halfNA;
        const float wqx = sQ[qw * 3 + 0];
        const float wqy = sQ[qw * 3 + 1];
        const float wqz = sQ[qw * 3 + 2];
        {
            int cnt = 0;
            for (int a = aBeg + lane; a < aEnd; a += 32) {
                const float ex = wqx - sApos[a * 3 + 0] + 1e-12f;
                const float ey = wqy - sApos[a * 3 + 1] + 1e-12f;
                const float ez = wqz - sApos[a * 3 + 2] + 1e-12f;
                const float d = sqrtf(ex * ex + ey * ey + ez * ez);
                unsigned m = __ballot_sync(0xffffffffu, d <= 6.0f);
                cnt += __popc(m);
            }
            if (lane == 0) sCnt[wid] = cnt;
        }
        __syncthreads();
        if (tid == 0) {
            int run = 0;
            #pragma unroll
            for (int w = 0; w < 4; w++) { sOff[w] = run; run += sCnt[w]; }
            sOff[4] = run;
        }
        __syncthreads();
        {
            int base = sOff[wid];
            for (int a = aBeg + lane; a < aEnd; a += 32) {
                const float ex = wqx - sApos[a * 3 + 0] + 1e-12f;
                const float ey = wqy - sApos[a * 3 + 1] + 1e-12f;
                const float ez = wqz - sApos[a * 3 + 2] + 1e-12f;
                const float d = sqrtf(ex * ex + ey * ey + ez * ez);
                const bool pred = (d <= 6.0f);
                unsigned m = __ballot_sync(0xffffffffu, pred);
                if (pred) sList[base + __popc(m & lanemask_lt)] =
                    (unsigned short)(((unsigned)qw << 9) | (unsigned)a);
                base += __popc(m);
            }
        }
        __syncthreads();

        const int total = sOff[4];

        // ---- Phase B: warp-local MMA over tiles of 128 pairs ----
        float wx0 = 0.f, wy0 = 0.f, wz0 = 0.f;
        float wx1 = 0.f, wy1 = 0.f, wz1 = 0.f;

        for (int base = 0; base < total; base += TPB) {
            const int i = base + wid * 32 + lane;
            const bool act = (i < total);

            float rx = 0.f, ry = 0.f, rz = 0.f, d = 1.f;
            int qs = 0;

            u32 hw[16], lw[16];
            #pragma unroll
            for (int j = 0; j < 16; j++) { hw[j] = 0; lw[j] = 0; }
            if (act) {
                const unsigned e = sList[i];
                qs = (int)(e >> 9);
                const int a = (int)(e & 511u);
                rx = sQ[qs * 3 + 0] - sApos[a * 3 + 0];
                ry = sQ[qs * 3 + 1] - sApos[a * 3 + 1];
                rz = sQ[qs * 3 + 2] - sApos[a * 3 + 2];
                const float ex = rx + 1e-12f, ey = ry + 1e-12f, ez = rz + 1e-12f;
                d = sqrtf(ex * ex + ey * ey + ez * ez);

                float xs[18];
                xs[0] = sAfeat[a * 2 + 0];
                xs[1] = sAfeat[a * 2 + 1];
                #pragma unroll
                for (int k = 0; k < 16; k++) {
                    const float ec = d - 0.4f * (float)k;
                    xs[2 + k] = __expf(-10.0f * ec * ec);
                }
                #pragma unroll
                for (int j = 0; j < 9; j++)
                    split2(xs[2 * j], xs[2 * j + 1], hw[j], lw[j]);
            }
            __syncwarp();
            {
                u64* xrow = (u64*)(pX + (wid * 32 + lane) * SX);
                #pragma unroll
                for (int j = 0; j < 8; j++)
                    xrow[j] = (u64)hw[2 * j] | ((u64)hw[2 * j + 1] << 32);
                #pragma unroll
                for (int j = 0; j < 8; j++)
                    xrow[8 + j] = (u64)lw[2 * j] | ((u64)lw[2 * j + 1] << 32);
            }
            __syncwarp();

            // ---- L1 ----
            float D1[2][8][4];
            #pragma unroll
            for (int m = 0; m < 2; m++)
                #pragma unroll
                for (int n = 0; n < 8; n++)
                    #pragma unroll
                    for (int c = 0; c < 4; c++) D1[m][n][c] = 0.f;

            #pragma unroll
            for (int kt = 0; kt < 2; kt++) {
                u32 ah[2][4], al[2][4];
                #pragma unroll
                for (int m = 0; m < 2; m++) {
                    const char* r0 = pX + (wid * 32 + m * 16 + g) * SX;
                    const char* r8 = r0 + 8 * SX;
                    const int w0 = (kt * 8 + t) * 4;
                    ah[m][0] = *(const u32*)(r0 + w0);
                    ah[m][1] = *(const u32*)(r8 + w0);
                    ah[m][2] = *(const u32*)(r0 + w0 + 16);
                    ah[m][3] = *(const u32*)(r8 + w0 + 16);
                    al[m][0] = *(const u32*)(r0 + w0 + 64);
                    al[m][1] = *(const u32*)(r8 + w0 + 64);
                    al[m][2] = *(const u32*)(r0 + w0 + 80);
                    al[m][3] = *(const u32*)(r8 + w0 + 80);
                }
                u32 bb[8][2];
                #pragma unroll
                for (int n = 0; n < 8; n++) {
                    const char* wh = sm + O_W1H + (8 * n + g) * S1 + kt * 32 + t * 4;
                    bb[n][0] = *(const u32*)wh;
                    bb[n][1] = *(const u32*)(wh + 16);
                }
                #pragma unroll
                for (int n = 0; n < 8; n++)
                    #pragma unroll
                    for (int m = 0; m < 2; m++)
                        mma16816(D1[m][n], ah[m], bb[n][0], bb[n][1]);
                #pragma unroll
                for (int n = 0; n < 8; n++)
                    #pragma unroll
                    for (int m = 0; m < 2; m++)
                        mma16816(D1[m][n], al[m], bb[n][0], bb[n][1]);
                #pragma unroll
                for (int n = 0; n < 8; n++) {
                    const char* wl = sm + O_W1L + (8 * n + g) * S1 + kt * 32 + t * 4;
                    bb[n][0] = *(const u32*)wl;
                    bb[n][1] = *(const u32*)(wl + 16);
                }
                #pragma unroll
                for (int n = 0; n < 8; n++)
                    #pragma unroll
                    for (int m = 0; m < 2; m++)
                        mma16816(D1[m][n], ah[m], bb[n][0], bb[n][1]);
            }

            // ---- epilogue 1 ----
            u32 ah2[2][4][4], al2[2][4][4];
            #pragma unroll
            for (int m = 0; m < 2; m++)
                #pragma unroll
                for (int kt = 0; kt < 4; kt++) {
                    const float2 ba = *(const float2*)(sb1f + kt * 16 + 2 * t);
                    const float2 bb2 = *(const float2*)(sb1f + kt * 16 + 8 + 2 * t);
                    const float* cA = D1[m][2 * kt];
                    const float* cB = D1[m][2 * kt + 1];
                    split2(fmaxf(cA[0] + ba.x, 0.f), fmaxf(cA[1] + ba.y, 0.f), ah2[m][kt][0], al2[m][kt][0]);
                    split2(fmaxf(cA[2] + ba.x, 0.f), fmaxf(cA[3] + ba.y, 0.f), ah2[m][kt][1], al2[m][kt][1]);
                    split2(fmaxf(cB[0] + bb2.x, 0.f), fmaxf(cB[1] + bb2.y, 0.f), ah2[m][kt][2], al2[m][kt][2]);
                    split2(fmaxf(cB[2] + bb2.x, 0.f), fmaxf(cB[3] + bb2.y, 0.f), ah2[m][kt][3], al2[m][kt][3]);
                }

            // ---- L2 ----
            float D2[2][8][4];
            #pragma unroll
            for (int m = 0; m < 2; m++)
                #pragma unroll
                for (int n = 0; n < 8; n++)
                    #pragma unroll
                    for (int c = 0; c < 4; c++) D2[m][n][c] = 0.f;

            #pragma unroll
            for (int kt = 0; kt < 4; kt++) {
                u32 bb[8][2];
                #pragma unroll
                for (int n = 0; n < 8; n++) {
                    const char* wh = sm + O_W2H + (8 * n + g) * S2 + kt * 32 + t * 4;
                    bb[n][0] = *(const u32*)wh;
                    bb[n][1] = *(const u32*)(wh + 16);
                }
                #pragma unroll
                for (int n = 0; n < 8; n++)
                    #pragma unroll
                    for (int m = 0; m < 2; m++)
                        mma16816(D2[m][n], ah2[m][kt], bb[n][0], bb[n][1]);
                #pragma unroll
                for (int n = 0; n < 8; n++)
                    #pragma unroll
                    for (int m = 0; m < 2; m++)
                        mma16816(D2[m][n], al2[m][kt], bb[n][0], bb[n][1]);
                #pragma unroll
                for (int n = 0; n < 8; n++) {
                    const char* wl = sm + O_W2L + (8 * n + g) * S2 + kt * 32 + t * 4;
                    bb[n][0] = *(const u32*)wl;
                    bb[n][1] = *(const u32*)(wl + 16);
                }
                #pragma unroll
                for (int n = 0; n < 8; n++)
                    #pragma unroll
                    for (int m = 0; m < 2; m++)
                        mma16816(D2[m][n], ah2[m][kt], bb[n][0], bb[n][1]);
            }

            // ---- epilogue 2 ----
            u32 ah3[2][4][4], al3[2][4][4];
            #pragma unroll
            for (int m = 0; m < 2; m++)
                #pragma unroll
                for (int kt = 0; kt < 4; kt++) {
                    const float2 ba = *(const float2*)(sb2f + kt * 16 + 2 * t);
                    const float2 bb2 = *(const float2*)(sb2f + kt * 16 + 8 + 2 * t);
                    const float* cA = D2[m][2 * kt];
                    const float* cB = D2[m][2 * kt + 1];
                    split2(fmaxf(cA[0] + ba.x, 0.f), fmaxf(cA[1] + ba.y, 0.f), ah3[m][kt][0], al3[m][kt][0]);
                    split2(fmaxf(cA[2] + ba.x, 0.f), fmaxf(cA[3] + ba.y, 0.f), ah3[m][kt][1], al3[m][kt][1]);
                    split2(fmaxf(cB[0] + bb2.x, 0.f), fmaxf(cB[1] + bb2.y, 0.f), ah3[m][kt][2], al3[m][kt][2]);
                    split2(fmaxf(cB[2] + bb2.x, 0.f), fmaxf(cB[3] + bb2.y, 0.f), ah3[m][kt][3], al3[m][kt][3]);
                }

            // ---- L3 ----
            float D3[2][4][4];
            #pragma unroll
            for (int m = 0; m < 2; m++)
                #pragma unroll
                for (int n = 0; n < 4; n++)
                    #pragma unroll
                    for (int c = 0; c < 4; c++) D3[m][n][c] = 0.f;

            #pragma unroll
            for (int kt = 0; kt < 4; kt++) {
                u32 bb[4][2];
                #pragma unroll
                for (int n = 0; n < 4; n++) {
                    const char* wh = sm + O_W3H + (8 * n + g) * S2 + kt * 32 + t * 4;
                    bb[n][0] = *(const u32*)wh;
                    bb[n][1] = *(const u32*)(wh + 16);
                }
                #pragma unroll
                for (int n = 0; n < 4; n++)
                    #pragma unroll
                    for (int m = 0; m < 2; m++)
                        mma16816(D3[m][n], ah3[m][kt], bb[n][0], bb[n][1]);
                #pragma unroll
                for (int n = 0; n < 4; n++)
                    #pragma unroll
                    for (int m = 0; m < 2; m++)
                        mma16816(D3[m][n], al3[m][kt], bb[n][0], bb[n][1]);
                #pragma unroll
                for (int n = 0; n < 4; n++) {
                    const char* wl = sm + O_W3L + (8 * n + g) * S2 + kt * 32 + t * 4;
                    bb[n][0] = *(const u32*)wl;
                    bb[n][1] = *(const u32*)(wl + 16);
                }
                #pragma unroll
                for (int n = 0; n < 4; n++)
                    #pragma unroll
                    for (int m = 0; m < 2; m++)
                        mma16816(D3[m][n], ah3[m][kt], bb[n][0], bb[n][1]);
            }

            // ---- epilogue 3 ----
            float S00 = 0.f, S01 = 0.f, S10 = 0.f, S11 = 0.f;
            #pragma unroll
            for (int nt = 0; nt < 4; nt++) {
                const float2 b3p = *(const float2*)(sb3f + nt * 8 + 2 * t);
                const float2 w4p = *(const float2*)(sW4f + nt * 8 + 2 * t);
                S00 += fmaxf(D3[0][nt][0] + b3p.x, 0.f) * w4p.x + fmaxf(D3[0][nt][1] + b3p.y, 0.f) * w4p.y;
                S01 += fmaxf(D3[0][nt][2] + b3p.x, 0.f) * w4p.x + fmaxf(D3[0][nt][3] + b3p.y, 0.f) * w4p.y;
                S10 += fmaxf(D3[1][nt][0] + b3p.x, 0.f) * w4p.x + fmaxf(D3[1][nt][1] + b3p.y, 0.f) * w4p.y;
                S11 += fmaxf(D3[1][nt][2] + b3p.x, 0.f) * w4p.x + fmaxf(D3[1][nt][3] + b3p.y, 0.f) * w4p.y;
            }
            #pragma unroll
            for (int off = 1; off <= 2; off <<= 1) {
                S00 += __shfl_xor_sync(0xffffffffu, S00, off);
                S01 += __shfl_xor_sync(0xffffffffu, S01, off);
                S10 += __shfl_xor_sync(0xffffffffu, S10, off);
                S11 += __shfl_xor_sync(0xffffffffu, S11, off);
            }
            __syncwarp();
            if (t == 0) {
                sSf[wid * 32 + g] = S00;
                sSf[wid * 32 + 8 + g] = S01;
                sSf[wid * 32 + 16 + g] = S10;
                sSf[wid * 32 + 24 + g] = S11;
            }
            __syncwarp();

            if (act) {
                const float s = sSf[wid * 32 + lane] + b4s;
                const float inv = 1.0f / (d + 1e-12f);
                const float cx = s * rx * inv;
                const float cy = s * ry * inv;
                const float cz = s * rz * inv;
                if (qs == 0) { wx0 += cx; wy0 += cy; wz0 += cz; }
                else         { wx1 += cx; wy1 += cy; wz1 += cz; }
            }
            __syncwarp();
        }

        __syncthreads();

        // ---- per-query reduction + final MLP 3->64->3 ----
        for (int qq = 0; qq < QPB; qq++) {
            const int q = grp * QPB + qq;

            float X = (qq == 0) ? wx0 : wx1;
            float Y = (qq == 0) ? wy0 : wy1;
            float Z = (qq == 0) ? wz0 : wz1;

            #pragma unroll
            for (int o = 16; o > 0; o >>= 1) {
                X += __shfl_down_sync(0xffffffffu, X, o);
                Y += __shfl_down_sync(0xffffffffu, Y, o);
                Z += __shfl_down_sync(0xffffffffu, Z, o);
            }
            if (lane == 0) {
                sRed[wid * 3 + 0] = X;
                sRed[wid * 3 + 1] = Y;
                sRed[wid * 3 + 2] = Z;
            }
            __syncthreads();
            if (tid == 0) {
                float Xs = 0, Ys = 0, Zs = 0;
                #pragma unroll
                for (int w = 0; w < 4; w++) {
                    Xs += sRed[w * 3 + 0];
                    Ys += sRed[w * 3 + 1];
                    Zs += sRed[w * 3 + 2];
                }
                sWgt[0] = Xs; sWgt[1] = Ys; sWgt[2] = Zs;
            }
            __syncthreads();

            float p0 = 0.0f, p1 = 0.0f, p2 = 0.0f;
            if (tid < 64) {
                const float Xs = sWgt[0], Ys = sWgt[1], Zs = sWgt[2];
                float hq = Xs * sW5[tid] + Ys * sW5[64 + tid] + Zs * sW5[128 + tid] + sb5[tid];
                hq = fmaxf(hq, 0.0f);
                p0 = hq * sW6[tid * 3 + 0];
                p1 = hq * sW6[tid * 3 + 1];
                p2 = hq * sW6[tid * 3 + 2];
            }
            #pragma unroll
            for (int o = 16; o > 0; o >>= 1) {
                p0 += __shfl_down_sync(0xffffffffu, p0, o);
                p1 += __shfl_down_sync(0xffffffffu, p1, o);
                p2 += __shfl_down_sync(0xffffffffu, p2, o);
            }
            if (tid == 0)  { sOut[0] = p0; sOut[1] = p1; sOut[2] = p2; }
            if (tid == 32) { sOut[3] = p0; sOut[4] = p1; sOut[5] = p2; }
            __syncthreads();
            if (tid == 0 && q < NQ) {
                out[q * 3 + 0] = sOut[0] + sOut[3] + b6[0];
                out[q * 3 + 1] = sOut[1] + sOut[4] + b6[1];
                out[q * 3 + 2] = sOut[2] + sOut[5] + b6[2];
            }
            __syncthreads();
        }
    }
}

extern "C" void kernel_launch(void* const* d_in, const int* in_sizes, int n_in,
                              void* d_out, int out_size) {
    const float* apos  = (const float*)d_in[0];
    const float* afeat = (const float*)d_in[1];
    const float* qpos  = (const float*)d_in[2];
    const float* W1 = (const float*)d_in[3];
    const float* b1 = (const float*)d_in[4];
    const float* W2 = (const float*)d_in[5];
    const float* b2 = (const float*)d_in[6];
    const float* W3 = (const float*)d_in[7];
    const float* b3 = (const float*)d_in[8];
    const float* W4 = (const float*)d_in[9];
    const float* b4 = (const float*)d_in[10];
    const float* W5 = (const float*)d_in[11];
    const float* b5 = (const float*)d_in[12];
    const float* W6 = (const float*)d_in[13];
    const float* b6 = (const float*)d_in[14];
    float* out = (float*)d_out;

    const int NA = in_sizes[0] / 3;
    const int NQ = in_sizes[2] / 3;

    cudaFuncSetAttribute(fieldnet_mma_kernel,
                         cudaFuncAttributeMaxDynamicSharedMemorySize, DYN_SMEM);

    reset_counter_kernel<<<1, 1>>>();
    fieldnet_mma_kernel<<<GRID, TPB, DYN_SMEM>>>(apos, afeat, qpos,
                                                 W1, b1, W2, b2, W3, b3, W4, b4,
                                                 W5, b5, W6, b6,
                                                 out, NA, NQ);
}

// round 13
// speedup vs baseline: 1.0817x; 1.0817x over previous
#include <cuda_runtime.h>
#include <cuda_bf16.h>

typedef unsigned int u32;
typedef unsigned long long u64;

#define TPB 128
#define GRID 444   // 148 SMs x 3 CTAs resident

// ---- dynamic SMEM layout (bytes) ----
#define O_W1H 0
#define O_W1L 5120
#define O_W2H 10240
#define O_W2L 19456
#define O_W3H 28672
#define O_W3L 33280
#define O_X   37888
#define O_APOS 56320
#define O_LIST 62464   // 4 warps x 512 u16
#define O_SS  66560    // 128 f32
#define O_AFEAT 67072
#define DYN_SMEM 71168

#define S1 80
#define S2 144
#define SX 144

__device__ int g_work_counter;

__global__ void reset_counter_kernel() { g_work_counter = 0; }

__device__ __forceinline__ u32 bpack(float v0, float v1) {
    u32 r;
    asm("cvt.rn.satfinite.bf16x2.f32 %0, %1, %2;" : "=r"(r) : "f"(v1), "f"(v0));
    return r;
}
__device__ __forceinline__ void split2(float v0, float v1, u32& hi, u32& lo) {
    const u32 ch = bpack(v0, v1);
    const float h0 = __uint_as_float(ch << 16);
    const float h1 = __uint_as_float(ch & 0xffff0000u);
    hi = ch;
    lo = bpack(v0 - h0, v1 - h1);
}
__device__ __forceinline__ void mma16816(float* d, const u32* a, u32 b0, u32 b1) {
    asm volatile(
        "mma.sync.aligned.m16n8k16.row.col.f32.bf16.bf16.f32 "
        "{%0,%1,%2,%3}, {%4,%5,%6,%7}, {%8,%9}, {%0,%1,%2,%3};"
        : "+f"(d[0]), "+f"(d[1]), "+f"(d[2]), "+f"(d[3])
        : "r"(a[0]), "r"(a[1]), "r"(a[2]), "r"(a[3]), "r"(b0), "r"(b1));
}

__global__ __launch_bounds__(TPB, 3)
void fieldnet_mma_kernel(
    const float* __restrict__ apos, const float* __restrict__ afeat,
    const float* __restrict__ qpos,
    const float* __restrict__ W1, const float* __restrict__ b1,
    const float* __restrict__ W2, const float* __restrict__ b2,
    const float* __restrict__ W3, const float* __restrict__ b3,
    const float* __restrict__ W4, const float* __restrict__ b4,
    const float* __restrict__ W5, const float* __restrict__ b5,
    const float* __restrict__ W6, const float* __restrict__ b6,
    float* __restrict__ out, int NA, int NQ)
{
    extern __shared__ __align__(16) char sm[];
    __shared__ __align__(16) float sb1f[64], sb2f[64], sb3f[32], sW4f[32];
    __shared__ __align__(16) float sW5[192], sW6[193], sb5[64];

    const int tid = threadIdx.x;
    const int lane = tid & 31;
    const int wid = tid >> 5;
    const int g = lane >> 2;
    const int t = lane & 3;
    const unsigned lanemask_lt = (1u << lane) - 1u;

    float* sApos = (float*)(sm + O_APOS);
    float* sAfeat = (float*)(sm + O_AFEAT);
    unsigned short* sListW = (unsigned short*)(sm + O_LIST) + wid * 512;
    float* sSf = (float*)(sm + O_SS);

    // ================= one-time per-CTA prep =================
    {
        u32* p = (u32*)sm;
        for (int i = tid; i < O_X / 4; i += TPB) p[i] = 0;
    }
    __syncthreads();

    for (int i = tid; i < NA * 3; i += TPB) sApos[i] = apos[i];
    for (int i = tid; i < NA * 2; i += TPB) sAfeat[i] = afeat[i];
    for (int i = tid; i < 3 * 64; i += TPB) { sW5[i] = W5[i]; sW6[i] = W6[i]; }
    if (tid < 64) { sb1f[tid] = b1[tid]; sb2f[tid] = b2[tid]; sb5[tid] = b5[tid]; }
    if (tid < 32) { sb3f[tid] = b3[tid]; sW4f[tid] = W4[tid]; }

    for (int i = tid; i < 18 * 64; i += TPB) {
        int k = i >> 6, n = i & 63;
        float v = W1[i];
        __nv_bfloat16 hb = __float2bfloat16(v);
        __nv_bfloat16 lb = __float2bfloat16(v - __bfloat162float(hb));
        *(unsigned short*)(sm + O_W1H + n * S1 + k * 2) = *(unsigned short*)&hb;
        *(unsigned short*)(sm + O_W1L + n * S1 + k * 2) = *(unsigned short*)&lb;
    }
    for (int i = tid; i < 64 * 64; i += TPB) {
        int k = i >> 6, n = i & 63;
        float v = W2[i];
        __nv_bfloat16 hb = __float2bfloat16(v);
        __nv_bfloat16 lb = __float2bfloat16(v - __bfloat162float(hb));
        *(unsigned short*)(sm + O_W2H + n * S2 + k * 2) = *(unsigned short*)&hb;
        *(unsigned short*)(sm + O_W2L + n * S2 + k * 2) = *(unsigned short*)&lb;
    }
    for (int i = tid; i < 64 * 32; i += TPB) {
        int k = i >> 5, n = i & 31;
        float v = W3[i];
        __nv_bfloat16 hb = __float2bfloat16(v);
        __nv_bfloat16 lb = __float2bfloat16(v - __bfloat162float(hb));
        *(unsigned short*)(sm + O_W3H + n * S2 + k * 2) = *(unsigned short*)&hb;
        *(unsigned short*)(sm + O_W3L + n * S2 + k * 2) = *(unsigned short*)&lb;
    }
    __syncthreads();   // prep complete; no block syncs after this point

    const float b4s = b4[0];
    const char* pX = sm + O_X;

    // ================= warp-autonomous query loop =================
    while (true) {
        int wq;
        if (lane == 0) wq = atomicAdd(&g_work_counter, 1);
        wq = __shfl_sync(0xffffffffu, wq, 0);
        if (wq >= NQ) break;

        const float qx = __ldg(qpos + wq * 3 + 0);
        const float qy = __ldg(qpos + wq * 3 + 1);
        const float qz = __ldg(qpos + wq * 3 + 2);

        // ---- warp-local compaction (single pass, no syncs) ----
        int cnt = 0;
        for (int a = lane; a < NA; a += 32) {
            const float ex = qx - sApos[a * 3 + 0] + 1e-12f;
            const float ey = qy - sApos[a * 3 + 1] + 1e-12f;
            const float ez = qz - sApos[a * 3 + 2] + 1e-12f;
            const float d = sqrtf(ex * ex + ey * ey + ez * ez);
            const bool pred = (d <= 6.0f);
            unsigned m = __ballot_sync(0xffffffffu, pred);
            if (pred) sListW[cnt + __popc(m & lanemask_lt)] = (unsigned short)a;
            cnt += __popc(m);
        }
        __syncwarp();

        float wx = 0.f, wy = 0.f, wz = 0.f;

        // ---- warp-tiles of 32 pairs ----
        for (int base = 0; base < cnt; base += 32) {
            const int i = base + lane;
            const bool act = (i < cnt);

            float rx = 0.f, ry = 0.f, rz = 0.f, d = 1.f;

            u32 hw[16], lw[16];
            #pragma unroll
            for (int j = 0; j < 16; j++) { hw[j] = 0; lw[j] = 0; }
            if (act) {
                const int a = (int)sListW[i];
                rx = qx - sApos[a * 3 + 0];
                ry = qy - sApos[a * 3 + 1];
                rz = qz - sApos[a * 3 + 2];
                const float ex = rx + 1e-12f, ey = ry + 1e-12f, ez = rz + 1e-12f;
                d = sqrtf(ex * ex + ey * ey + ez * ez);

                float xs[18];
                xs[0] = sAfeat[a * 2 + 0];
                xs[1] = sAfeat[a * 2 + 1];
                #pragma unroll
                for (int k = 0; k < 16; k++) {
                    const float ec = d - 0.4f * (float)k;
                    xs[2 + k] = __expf(-10.0f * ec * ec);
                }
                #pragma unroll
                for (int j = 0; j < 9; j++)
                    split2(xs[2 * j], xs[2 * j + 1], hw[j], lw[j]);
            }
            __syncwarp();
            {
                u64* xrow = (u64*)(pX + (wid * 32 + lane) * SX);
                #pragma unroll
                for (int j = 0; j < 8; j++)
                    xrow[j] = (u64)hw[2 * j] | ((u64)hw[2 * j + 1] << 32);
                #pragma unroll
                for (int j = 0; j < 8; j++)
                    xrow[8 + j] = (u64)lw[2 * j] | ((u64)lw[2 * j + 1] << 32);
            }
            __syncwarp();

            // ---- L1 ----
            float D1[2][8][4];
            #pragma unroll
            for (int m = 0; m < 2; m++)
                #pragma unroll
                for (int n = 0; n < 8; n++)
                    #pragma unroll
                    for (int c = 0; c < 4; c++) D1[m][n][c] = 0.f;

            #pragma unroll
            for (int kt = 0; kt < 2; kt++) {
                u32 ah[2][4], al[2][4];
                #pragma unroll
                for (int m = 0; m < 2; m++) {
                    const char* r0 = pX + (wid * 32 + m * 16 + g) * SX;
                    const char* r8 = r0 + 8 * SX;
                    const int w0 = (kt * 8 + t) * 4;
                    ah[m][0] = *(const u32*)(r0 + w0);
                    ah[m][1] = *(const u32*)(r8 + w0);
                    ah[m][2] = *(const u32*)(r0 + w0 + 16);
                    ah[m][3] = *(const u32*)(r8 + w0 + 16);
                    al[m][0] = *(const u32*)(r0 + w0 + 64);
                    al[m][1] = *(const u32*)(r8 + w0 + 64);
                    al[m][2] = *(const u32*)(r0 + w0 + 80);
                    al[m][3] = *(const u32*)(r8 + w0 + 80);
                }
                u32 bb[8][2];
                #pragma unroll
                for (int n = 0; n < 8; n++) {
                    const char* wh = sm + O_W1H + (8 * n + g) * S1 + kt * 32 + t * 4;
                    bb[n][0] = *(const u32*)wh;
                    bb[n][1] = *(const u32*)(wh + 16);
                }
                #pragma unroll
                for (int n = 0; n < 8; n++)
                    #pragma unroll
                    for (int m = 0; m < 2; m++)
                        mma16816(D1[m][n], ah[m], bb[n][0], bb[n][1]);
                #pragma unroll
                for (int n = 0; n < 8; n++)
                    #pragma unroll
                    for (int m = 0; m < 2; m++)
                        mma16816(D1[m][n], al[m], bb[n][0], bb[n][1]);
                #pragma unroll
                for (int n = 0; n < 8; n++) {
                    const char* wl = sm + O_W1L + (8 * n + g) * S1 + kt * 32 + t * 4;
                    bb[n][0] = *(const u32*)wl;
                    bb[n][1] = *(const u32*)(wl + 16);
                }
                #pragma unroll
                for (int n = 0; n < 8; n++)
                    #pragma unroll
                    for (int m = 0; m < 2; m++)
                        mma16816(D1[m][n], ah[m], bb[n][0], bb[n][1]);
            }

            // ---- epilogue 1 ----
            u32 ah2[2][4][4], al2[2][4][4];
            #pragma unroll
            for (int m = 0; m < 2; m++)
                #pragma unroll
                for (int kt = 0; kt < 4; kt++) {
                    const float2 ba = *(const float2*)(sb1f + kt * 16 + 2 * t);
                    const float2 bb2 = *(const float2*)(sb1f + kt * 16 + 8 + 2 * t);
                    const float* cA = D1[m][2 * kt];
                    const float* cB = D1[m][2 * kt + 1];
                    split2(fmaxf(cA[0] + ba.x, 0.f), fmaxf(cA[1] + ba.y, 0.f), ah2[m][kt][0], al2[m][kt][0]);
                    split2(fmaxf(cA[2] + ba.x, 0.f), fmaxf(cA[3] + ba.y, 0.f), ah2[m][kt][1], al2[m][kt][1]);
                    split2(fmaxf(cB[0] + bb2.x, 0.f), fmaxf(cB[1] + bb2.y, 0.f), ah2[m][kt][2], al2[m][kt][2]);
                    split2(fmaxf(cB[2] + bb2.x, 0.f), fmaxf(cB[3] + bb2.y, 0.f), ah2[m][kt][3], al2[m][kt][3]);
                }

            // ---- L2 ----
            float D2[2][8][4];
            #pragma unroll
            for (int m = 0; m < 2; m++)
                #pragma unroll
                for (int n = 0; n < 8; n++)
                    #pragma unroll
                    for (int c = 0; c < 4; c++) D2[m][n][c] = 0.f;

            #pragma unroll
            for (int kt = 0; kt < 4; kt++) {
                u32 bb[8][2];
                #pragma unroll
                for (int n = 0; n < 8; n++) {
                    const char* wh = sm + O_W2H + (8 * n + g) * S2 + kt * 32 + t * 4;
                    bb[n][0] = *(const u32*)wh;
                    bb[n][1] = *(const u32*)(wh + 16);
                }
                #pragma unroll
                for (int n = 0; n < 8; n++)
                    #pragma unroll
                    for (int m = 0; m < 2; m++)
                        mma16816(D2[m][n], ah2[m][kt], bb[n][0], bb[n][1]);
                #pragma unroll
                for (int n = 0; n < 8; n++)
                    #pragma unroll
                    for (int m = 0; m < 2; m++)
                        mma16816(D2[m][n], al2[m][kt], bb[n][0], bb[n][1]);
                #pragma unroll
                for (int n = 0; n < 8; n++) {
                    const char* wl = sm + O_W2L + (8 * n + g) * S2 + kt * 32 + t * 4;
                    bb[n][0] = *(const u32*)wl;
                    bb[n][1] = *(const u32*)(wl + 16);
                }
                #pragma unroll
                for (int n = 0; n < 8; n++)
                    #pragma unroll
                    for (int m = 0; m < 2; m++)
                        mma16816(D2[m][n], ah2[m][kt], bb[n][0], bb[n][1]);
            }

            // ---- epilogue 2 ----
            u32 ah3[2][4][4], al3[2][4][4];
            #pragma unroll
            for (int m = 0; m < 2; m++)
                #pragma unroll
                for (int kt = 0; kt < 4; kt++) {
                    const float2 ba = *(const float2*)(sb2f + kt * 16 + 2 * t);
                    const float2 bb2 = *(const float2*)(sb2f + kt * 16 + 8 + 2 * t);
                    const float* cA = D2[m][2 * kt];
                    const float* cB = D2[m][2 * kt + 1];
                    split2(fmaxf(cA[0] + ba.x, 0.f), fmaxf(cA[1] + ba.y, 0.f), ah3[m][kt][0], al3[m][kt][0]);
                    split2(fmaxf(cA[2] + ba.x, 0.f), fmaxf(cA[3] + ba.y, 0.f), ah3[m][kt][1], al3[m][kt][1]);
                    split2(fmaxf(cB[0] + bb2.x, 0.f), fmaxf(cB[1] + bb2.y, 0.f), ah3[m][kt][2], al3[m][kt][2]);
                    split2(fmaxf(cB[2] + bb2.x, 0.f), fmaxf(cB[3] + bb2.y, 0.f), ah3[m][kt][3], al3[m][kt][3]);
                }

            // ---- L3 ----
            float D3[2][4][4];
            #pragma unroll
            for (int m = 0; m < 2; m++)
                #pragma unroll
                for (int n = 0; n < 4; n++)
                    #pragma unroll
                    for (int c = 0; c < 4; c++) D3[m][n][c] = 0.f;

            #pragma unroll
            for (int kt = 0; kt < 4; kt++) {
                u32 bb[4][2];
                #pragma unroll
                for (int n = 0; n < 4; n++) {
                    const char* wh = sm + O_W3H + (8 * n + g) * S2 + kt * 32 + t * 4;
                    bb[n][0] = *(const u32*)wh;
                    bb[n][1] = *(const u32*)(wh + 16);
                }
                #pragma unroll
                for (int n = 0; n < 4; n++)
                    #pragma unroll
                    for (int m = 0; m < 2; m++)
                        mma16816(D3[m][n], ah3[m][kt], bb[n][0], bb[n][1]);
                #pragma unroll
                for (int n = 0; n < 4; n++)
                    #pragma unroll
                    for (int m = 0; m < 2; m++)
                        mma16816(D3[m][n], al3[m][kt], bb[n][0], bb[n][1]);
                #pragma unroll
                for (int n = 0; n < 4; n++) {
                    const char* wl = sm + O_W3L + (8 * n + g) * S2 + kt * 32 + t * 4;
                    bb[n][0] = *(const u32*)wl;
                    bb[n][1] = *(const u32*)(wl + 16);
                }
                #pragma unroll
                for (int n = 0; n < 4; n++)
                    #pragma unroll
                    for (int m = 0; m < 2; m++)
                        mma16816(D3[m][n], ah3[m][kt], bb[n][0], bb[n][1]);
            }

            // ---- epilogue 3: relu(D3+b3).W4 per row, cross-t reduce ----
            float S00 = 0.f, S01 = 0.f, S10 = 0.f, S11 = 0.f;
            #pragma unroll
            for (int nt = 0; nt < 4; nt++) {
                const float2 b3p = *(const float2*)(sb3f + nt * 8 + 2 * t);
                const float2 w4p = *(const float2*)(sW4f + nt * 8 + 2 * t);
                S00 += fmaxf(D3[0][nt][0] + b3p.x, 0.f) * w4p.x + fmaxf(D3[0][nt][1] + b3p.y, 0.f) * w4p.y;
                S01 += fmaxf(D3[0][nt][2] + b3p.x, 0.f) * w4p.x + fmaxf(D3[0][nt][3] + b3p.y, 0.f) * w4p.y;
                S10 += fmaxf(D3[1][nt][0] + b3p.x, 0.f) * w4p.x + fmaxf(D3[1][nt][1] + b3p.y, 0.f) * w4p.y;
                S11 += fmaxf(D3[1][nt][2] + b3p.x, 0.f) * w4p.x + fmaxf(D3[1][nt][3] + b3p.y, 0.f) * w4p.y;
            }
            #pragma unroll
            for (int off = 1; off <= 2; off <<= 1) {
                S00 += __shfl_xor_sync(0xffffffffu, S00, off);
                S01 += __shfl_xor_sync(0xffffffffu, S01, off);
                S10 += __shfl_xor_sync(0xffffffffu, S10, off);
                S11 += __shfl_xor_sync(0xffffffffu, S11, off);
            }
            __syncwarp();
            if (t == 0) {
                sSf[wid * 32 + g] = S00;
                sSf[wid * 32 + 8 + g] = S01;
                sSf[wid * 32 + 16 + g] = S10;
                sSf[wid * 32 + 24 + g] = S11;
            }
            __syncwarp();

            if (act) {
                const float s = sSf[wid * 32 + lane] + b4s;
                const float inv = 1.0f / (d + 1e-12f);
                wx = fmaf(s * rx, inv, wx);
                wy = fmaf(s * ry, inv, wy);
                wz = fmaf(s * rz, inv, wz);
            }
            __syncwarp();
        }

        // ---- in-warp reduction + final MLP 3->64->3 ----
        #pragma unroll
        for (int o = 16; o > 0; o >>= 1) {
            wx += __shfl_down_sync(0xffffffffu, wx, o);
            wy += __shfl_down_sync(0xffffffffu, wy, o);
            wz += __shfl_down_sync(0xffffffffu, wz, o);
        }
        const float X = __shfl_sync(0xffffffffu, wx, 0);
        const float Y = __shfl_sync(0xffffffffu, wy, 0);
        const float Z = __shfl_sync(0xffffffffu, wz, 0);

        float p0 = 0.f, p1 = 0.f, p2 = 0.f;
        #pragma unroll
        for (int uu = 0; uu < 2; uu++) {
            const int u = lane + uu * 32;
            float hq = X * sW5[u] + Y * sW5[64 + u] + Z * sW5[128 + u] + sb5[u];
            hq = fmaxf(hq, 0.0f);
            p0 = fmaf(hq, sW6[u * 3 + 0], p0);
            p1 = fmaf(hq, sW6[u * 3 + 1], p1);
            p2 = fmaf(hq, sW6[u * 3 + 2], p2);
        }
        #pragma unroll
        for (int o = 16; o > 0; o >>= 1) {
            p0 += __shfl_down_sync(0xffffffffu, p0, o);
            p1 += __shfl_down_sync(0xffffffffu, p1, o);
            p2 += __shfl_down_sync(0xffffffffu, p2, o);
        }
        if (lane == 0) {
            out[wq * 3 + 0] = p0 + b6[0];
            out[wq * 3 + 1] = p1 + b6[1];
            out[wq * 3 + 2] = p2 + b6[2];
        }
    }
}

extern "C" void kernel_launch(void* const* d_in, const int* in_sizes, int n_in,
                              void* d_out, int out_size) {
    const float* apos  = (const float*)d_in[0];
    const float* afeat = (const float*)d_in[1];
    const float* qpos  = (const float*)d_in[2];
    const float* W1 = (const float*)d_in[3];
    const float* b1 = (const float*)d_in[4];
    const float* W2 = (const float*)d_in[5];
    const float* b2 = (const float*)d_in[6];
    const float* W3 = (const float*)d_in[7];
    const float* b3 = (const float*)d_in[8];
    const float* W4 = (const float*)d_in[9];
    const float* b4 = (const float*)d_in[10];
    const float* W5 = (const float*)d_in[11];
    const float* b5 = (const float*)d_in[12];
    const float* W6 = (const float*)d_in[13];
    const float* b6 = (const float*)d_in[14];
    float* out = (float*)d_out;

    const int NA = in_sizes[0] / 3;
    const int NQ = in_sizes[2] / 3;

    cudaFuncSetAttribute(fieldnet_mma_kernel,
                         cudaFuncAttributeMaxDynamicSharedMemorySize, DYN_SMEM);

    reset_counter_kernel<<<1, 1>>>();
    fieldnet_mma_kernel<<<GRID, TPB, DYN_SMEM>>>(apos, afeat, qpos,
                                                 W1, b1, W2, b2, W3, b3, W4, b4,
                                                 W5, b5, W6, b6,
                                                 out, NA, NQ);
}

// round 14
// speedup vs baseline: 1.1638x; 1.0759x over previous
#include <cuda_runtime.h>
#include <cuda_bf16.h>

typedef unsigned int u32;
typedef unsigned long long u64;

#define TPB 128
#define QPB 4

// ---- dynamic SMEM layout (bytes) ----
#define O_W1S 0        // 64 n-rows x 144B: k0-17=Wh, k18-35=Wh, k36-53=Wl, rest 0
#define O_W2H 9216
#define O_W2L 18432
#define O_W3H 27648
#define O_W3L 32256
#define O_X   36864    // 128 rows x 144B: halves 0-17=xh, 18-35=xl, 36-53=xh, rest 0
#define O_APOS 55296
#define O_LIST 61440
#define O_SS  65536
#define O_AFEAT 66048
#define DYN_SMEM 70144

#define S1 144
#define S2 144
#define SX 144

__device__ __forceinline__ u32 bpack(float v0, float v1) {
    u32 r;
    asm("cvt.rn.satfinite.bf16x2.f32 %0, %1, %2;" : "=r"(r) : "f"(v1), "f"(v0));
    return r;
}
__device__ __forceinline__ void split2(float v0, float v1, u32& hi, u32& lo) {
    const u32 ch = bpack(v0, v1);
    const float h0 = __uint_as_float(ch << 16);
    const float h1 = __uint_as_float(ch & 0xffff0000u);
    hi = ch;
    lo = bpack(v0 - h0, v1 - h1);
}
__device__ __forceinline__ void mma16816(float* d, const u32* a, u32 b0, u32 b1) {
    asm volatile(
        "mma.sync.aligned.m16n8k16.row.col.f32.bf16.bf16.f32 "
        "{%0,%1,%2,%3}, {%4,%5,%6,%7}, {%8,%9}, {%0,%1,%2,%3};"
        : "+f"(d[0]), "+f"(d[1]), "+f"(d[2]), "+f"(d[3])
        : "r"(a[0]), "r"(a[1]), "r"(a[2]), "r"(a[3]), "r"(b0), "r"(b1));
}

__global__ __launch_bounds__(TPB, 3)
void fieldnet_mma_kernel(
    const float* __restrict__ apos, const float* __restrict__ afeat,
    const float* __restrict__ qpos,
    const float* __restrict__ W1, const float* __restrict__ b1,
    const float* __restrict__ W2, const float* __restrict__ b2,
    const float* __restrict__ W3, const float* __restrict__ b3,
    const float* __restrict__ W4, const float* __restrict__ b4,
    const float* __restrict__ W5, const float* __restrict__ b5,
    const float* __restrict__ W6, const float* __restrict__ b6,
    float* __restrict__ out, int NA, int NQ)
{
    extern __shared__ __align__(16) char sm[];
    __shared__ __align__(16) float sb1f[64], sb2f[64], sb3f[32], sW4f[32];
    __shared__ __align__(16) float sW5[192], sW6[193], sb5[64];
    __shared__ float sQ[QPB * 3], sRed[12], sWgt[3], sOut[6];
    __shared__ int sCnt[QPB], sOff[QPB + 1];

    const int tid = threadIdx.x;
    const int lane = tid & 31;
    const int wid = tid >> 5;
    const int g = lane >> 2;
    const int t = lane & 3;
    const unsigned lanemask_lt = (1u << lane) - 1u;

    float* sApos = (float*)(sm + O_APOS);
    float* sAfeat = (float*)(sm + O_AFEAT);
    unsigned short* sList = (unsigned short*)(sm + O_LIST);
    float* sSf = (float*)(sm + O_SS);

    // ---- zero weight regions (padding must be zero) ----
    {
        u32* p = (u32*)sm;
        for (int i = tid; i < O_X / 4; i += TPB) p[i] = 0;
    }
    __syncthreads();

    for (int i = tid; i < NA * 3; i += TPB) sApos[i] = apos[i];
    for (int i = tid; i < NA * 2; i += TPB) sAfeat[i] = afeat[i];
    for (int i = tid; i < 3 * 64; i += TPB) { sW5[i] = W5[i]; sW6[i] = W6[i]; }
    if (tid < 64) { sb1f[tid] = b1[tid]; sb2f[tid] = b2[tid]; sb5[tid] = b5[tid]; }
    if (tid < 32) { sb3f[tid] = b3[tid]; sW4f[tid] = W4[tid]; }
    if (tid < QPB * 3) {
        int qg = blockIdx.x * QPB + tid / 3;
        sQ[tid] = (qg < NQ) ? qpos[qg * 3 + (tid % 3)] : 1e30f;
    }

    // ---- W1 stacked: rows n, halves k=Wh, 18+k=Wh, 36+k=Wl ----
    for (int i = tid; i < 18 * 64; i += TPB) {
        int k = i >> 6, n = i & 63;
        float v = W1[i];
        __nv_bfloat16 hb = __float2bfloat16(v);
        __nv_bfloat16 lb = __float2bfloat16(v - __bfloat162float(hb));
        *(unsigned short*)(sm + O_W1S + n * S1 + k * 2) = *(unsigned short*)&hb;
        *(unsigned short*)(sm + O_W1S + n * S1 + (18 + k) * 2) = *(unsigned short*)&hb;
        *(unsigned short*)(sm + O_W1S + n * S1 + (36 + k) * 2) = *(unsigned short*)&lb;
    }
    for (int i = tid; i < 64 * 64; i += TPB) {
        int k = i >> 6, n = i & 63;
        float v = W2[i];
        __nv_bfloat16 hb = __float2bfloat16(v);
        __nv_bfloat16 lb = __float2bfloat16(v - __bfloat162float(hb));
        *(unsigned short*)(sm + O_W2H + n * S2 + k * 2) = *(unsigned short*)&hb;
        *(unsigned short*)(sm + O_W2L + n * S2 + k * 2) = *(unsigned short*)&lb;
    }
    for (int i = tid; i < 64 * 32; i += TPB) {
        int k = i >> 5, n = i & 31;
        float v = W3[i];
        __nv_bfloat16 hb = __float2bfloat16(v);
        __nv_bfloat16 lb = __float2bfloat16(v - __bfloat162float(hb));
        *(unsigned short*)(sm + O_W3H + n * S2 + k * 2) = *(unsigned short*)&hb;
        *(unsigned short*)(sm + O_W3L + n * S2 + k * 2) = *(unsigned short*)&lb;
    }
    __syncthreads();

    const float b4s = b4[0];

    // ---- Phase A: cutoff culling, deterministic two-pass compaction ----
    const float wqx = sQ[wid * 3 + 0];
    const float wqy = sQ[wid * 3 + 1];
    const float wqz = sQ[wid * 3 + 2];
    {
        int cnt = 0;
        for (int a = lane; a < NA; a += 32) {
            const float ex = wqx - sApos[a * 3 + 0] + 1e-12f;
            const float ey = wqy - sApos[a * 3 + 1] + 1e-12f;
            const float ez = wqz - sApos[a * 3 + 2] + 1e-12f;
            const float d = sqrtf(ex * ex + ey * ey + ez * ez);
            unsigned m = __ballot_sync(0xffffffffu, d <= 6.0f);
            cnt += __popc(m);
        }
        if (lane == 0) sCnt[wid] = cnt;
    }
    __syncthreads();
    if (tid == 0) {
        int run = 0;
        #pragma unroll
        for (int w = 0; w < QPB; w++) { sOff[w] = run; run += sCnt[w]; }
        sOff[QPB] = run;
    }
    __syncthreads();
    {
        int base = sOff[wid];
        for (int a = lane; a < NA; a += 32) {
            const float ex = wqx - sApos[a * 3 + 0] + 1e-12f;
            const float ey = wqy - sApos[a * 3 + 1] + 1e-12f;
            const float ez = wqz - sApos[a * 3 + 2] + 1e-12f;
            const float d = sqrtf(ex * ex + ey * ey + ez * ez);
            const bool pred = (d <= 6.0f);
            unsigned m = __ballot_sync(0xffffffffu, pred);
            if (pred) sList[base + __popc(m & lanemask_lt)] =
                (unsigned short)(((unsigned)wid << 9) | (unsigned)a);
            base += __popc(m);
        }
    }
    __syncthreads();

    const int total = sOff[QPB];

    // ---- Phase B: warp-local MMA over tiles of 128 pairs ----
    float wx0 = 0.f, wy0 = 0.f, wz0 = 0.f;
    float wx1 = 0.f, wy1 = 0.f, wz1 = 0.f;
    float wx2 = 0.f, wy2 = 0.f, wz2 = 0.f;
    float wx3 = 0.f, wy3 = 0.f, wz3 = 0.f;

    const char* pX = sm + O_X;

    for (int base = 0; base < total; base += TPB) {
        const int i = base + wid * 32 + lane;
        const bool act = (i < total);

        float rx = 0.f, ry = 0.f, rz = 0.f, d = 1.f;
        int qs = 0;

        // ---- stage input row: halves 0-17=xh, 18-35=xl, 36-53=xh, 54-63=0 ----
        u32 hw[9], lw[9];
        #pragma unroll
        for (int j = 0; j < 9; j++) { hw[j] = 0; lw[j] = 0; }
        if (act) {
            const unsigned e = sList[i];
            qs = (int)(e >> 9);
            const int a = (int)(e & 511u);
            rx = sQ[qs * 3 + 0] - sApos[a * 3 + 0];
            ry = sQ[qs * 3 + 1] - sApos[a * 3 + 1];
            rz = sQ[qs * 3 + 2] - sApos[a * 3 + 2];
            const float ex = rx + 1e-12f, ey = ry + 1e-12f, ez = rz + 1e-12f;
            d = sqrtf(ex * ex + ey * ey + ez * ez);

            float xs[18];
            xs[0] = sAfeat[a * 2 + 0];
            xs[1] = sAfeat[a * 2 + 1];
            #pragma unroll
            for (int k = 0; k < 16; k++) {
                const float ec = d - 0.4f * (float)k;
                xs[2 + k] = __expf(-10.0f * ec * ec);
            }
            #pragma unroll
            for (int j = 0; j < 9; j++)
                split2(xs[2 * j], xs[2 * j + 1], hw[j], lw[j]);
        }
        __syncwarp();
        {
            u64* xrow = (u64*)(pX + (wid * 32 + lane) * SX);
            // words: 0-8 = hw, 9-17 = lw, 18-26 = hw, 27-31 = 0
            xrow[0] = (u64)hw[0] | ((u64)hw[1] << 32);
            xrow[1] = (u64)hw[2] | ((u64)hw[3] << 32);
            xrow[2] = (u64)hw[4] | ((u64)hw[5] << 32);
            xrow[3] = (u64)hw[6] | ((u64)hw[7] << 32);
            xrow[4] = (u64)hw[8] | ((u64)lw[0] << 32);
            xrow[5] = (u64)lw[1] | ((u64)lw[2] << 32);
            xrow[6] = (u64)lw[3] | ((u64)lw[4] << 32);
            xrow[7] = (u64)lw[5] | ((u64)lw[6] << 32);
            xrow[8] = (u64)lw[7] | ((u64)lw[8] << 32);
            xrow[9] = (u64)hw[0] | ((u64)hw[1] << 32);
            xrow[10] = (u64)hw[2] | ((u64)hw[3] << 32);
            xrow[11] = (u64)hw[4] | ((u64)hw[5] << 32);
            xrow[12] = (u64)hw[6] | ((u64)hw[7] << 32);
            xrow[13] = (u64)hw[8];
            xrow[14] = 0;
            xrow[15] = 0;
        }
        __syncwarp();

        // ---- L1 fused: D1 = [xh|xl|xh] @ [Wh;Wh;Wl], bias-init, 4 k-tiles ----
        float D1[2][8][4];
        #pragma unroll
        for (int kt4 = 0; kt4 < 4; kt4++) {
            const float2 ba = *(const float2*)(sb1f + kt4 * 16 + 2 * t);
            const float2 bb2 = *(const float2*)(sb1f + kt4 * 16 + 8 + 2 * t);
            #pragma unroll
            for (int m = 0; m < 2; m++) {
                D1[m][2 * kt4][0] = ba.x;  D1[m][2 * kt4][1] = ba.y;
                D1[m][2 * kt4][2] = ba.x;  D1[m][2 * kt4][3] = ba.y;
                D1[m][2 * kt4 + 1][0] = bb2.x; D1[m][2 * kt4 + 1][1] = bb2.y;
                D1[m][2 * kt4 + 1][2] = bb2.x; D1[m][2 * kt4 + 1][3] = bb2.y;
            }
        }

        #pragma unroll
        for (int kt = 0; kt < 4; kt++) {
            u32 av[2][4];
            #pragma unroll
            for (int m = 0; m < 2; m++) {
                const char* r0 = pX + (wid * 32 + m * 16 + g) * SX;
                const char* r8 = r0 + 8 * SX;
                const int w0 = (kt * 8 + t) * 4;
                av[m][0] = *(const u32*)(r0 + w0);
                av[m][1] = *(const u32*)(r8 + w0);
                av[m][2] = *(const u32*)(r0 + w0 + 16);
                av[m][3] = *(const u32*)(r8 + w0 + 16);
            }
            u32 bb[8][2];
            #pragma unroll
            for (int n = 0; n < 8; n++) {
                const char* wp = sm + O_W1S + (8 * n + g) * S1 + kt * 32 + t * 4;
                bb[n][0] = *(const u32*)wp;
                bb[n][1] = *(const u32*)(wp + 16);
            }
            #pragma unroll
            for (int n = 0; n < 8; n++)
                #pragma unroll
                for (int m = 0; m < 2; m++)
                    mma16816(D1[m][n], av[m], bb[n][0], bb[n][1]);
        }

        // ---- epilogue 1: relu -> A2 fragments (bias already in D) ----
        u32 ah2[2][4][4], al2[2][4][4];
        #pragma unroll
        for (int m = 0; m < 2; m++)
            #pragma unroll
            for (int kt = 0; kt < 4; kt++) {
                const float* cA = D1[m][2 * kt];
                const float* cB = D1[m][2 * kt + 1];
                split2(fmaxf(cA[0], 0.f), fmaxf(cA[1], 0.f), ah2[m][kt][0], al2[m][kt][0]);
                split2(fmaxf(cA[2], 0.f), fmaxf(cA[3], 0.f), ah2[m][kt][1], al2[m][kt][1]);
                split2(fmaxf(cB[0], 0.f), fmaxf(cB[1], 0.f), ah2[m][kt][2], al2[m][kt][2]);
                split2(fmaxf(cB[2], 0.f), fmaxf(cB[3], 0.f), ah2[m][kt][3], al2[m][kt][3]);
            }

        // ---- L2: bias-init, 4kt x 3 term-major passes ----
        float D2[2][8][4];
        #pragma unroll
        for (int kt4 = 0; kt4 < 4; kt4++) {
            const float2 ba = *(const float2*)(sb2f + kt4 * 16 + 2 * t);
            const float2 bb2 = *(const float2*)(sb2f + kt4 * 16 + 8 + 2 * t);
            #pragma unroll
            for (int m = 0; m < 2; m++) {
                D2[m][2 * kt4][0] = ba.x;  D2[m][2 * kt4][1] = ba.y;
                D2[m][2 * kt4][2] = ba.x;  D2[m][2 * kt4][3] = ba.y;
                D2[m][2 * kt4 + 1][0] = bb2.x; D2[m][2 * kt4 + 1][1] = bb2.y;
                D2[m][2 * kt4 + 1][2] = bb2.x; D2[m][2 * kt4 + 1][3] = bb2.y;
            }
        }

        #pragma unroll
        for (int kt = 0; kt < 4; kt++) {
            u32 bb[8][2];
            #pragma unroll
            for (int n = 0; n < 8; n++) {
                const char* wh = sm + O_W2H + (8 * n + g) * S2 + kt * 32 + t * 4;
                bb[n][0] = *(const u32*)wh;
                bb[n][1] = *(const u32*)(wh + 16);
            }
            #pragma unroll
            for (int n = 0; n < 8; n++)
                #pragma unroll
                for (int m = 0; m < 2; m++)
                    mma16816(D2[m][n], ah2[m][kt], bb[n][0], bb[n][1]);
            #pragma unroll
            for (int n = 0; n < 8; n++)
                #pragma unroll
                for (int m = 0; m < 2; m++)
                    mma16816(D2[m][n], al2[m][kt], bb[n][0], bb[n][1]);
            #pragma unroll
            for (int n = 0; n < 8; n++) {
                const char* wl = sm + O_W2L + (8 * n + g) * S2 + kt * 32 + t * 4;
                bb[n][0] = *(const u32*)wl;
                bb[n][1] = *(const u32*)(wl + 16);
            }
            #pragma unroll
            for (int n = 0; n < 8; n++)
                #pragma unroll
                for (int m = 0; m < 2; m++)
                    mma16816(D2[m][n], ah2[m][kt], bb[n][0], bb[n][1]);
        }

        // ---- epilogue 2: relu -> A3 fragments ----
        u32 ah3[2][4][4], al3[2][4][4];
        #pragma unroll
        for (int m = 0; m < 2; m++)
            #pragma unroll
            for (int kt = 0; kt < 4; kt++) {
                const float* cA = D2[m][2 * kt];
                const float* cB = D2[m][2 * kt + 1];
                split2(fmaxf(cA[0], 0.f), fmaxf(cA[1], 0.f), ah3[m][kt][0], al3[m][kt][0]);
                split2(fmaxf(cA[2], 0.f), fmaxf(cA[3], 0.f), ah3[m][kt][1], al3[m][kt][1]);
                split2(fmaxf(cB[0], 0.f), fmaxf(cB[1], 0.f), ah3[m][kt][2], al3[m][kt][2]);
                split2(fmaxf(cB[2], 0.f), fmaxf(cB[3], 0.f), ah3[m][kt][3], al3[m][kt][3]);
            }

        // ---- L3: bias-init, N=32 ----
        float D3[2][4][4];
        #pragma unroll
        for (int nt = 0; nt < 4; nt++) {
            const float2 b3p = *(const float2*)(sb3f + nt * 8 + 2 * t);
            #pragma unroll
            for (int m = 0; m < 2; m++) {
                D3[m][nt][0] = b3p.x; D3[m][nt][1] = b3p.y;
                D3[m][nt][2] = b3p.x; D3[m][nt][3] = b3p.y;
            }
        }

        #pragma unroll
        for (int kt = 0; kt < 4; kt++) {
            u32 bb[4][2];
            #pragma unroll
            for (int n = 0; n < 4; n++) {
                const char* wh = sm + O_W3H + (8 * n + g) * S2 + kt * 32 + t * 4;
                bb[n][0] = *(const u32*)wh;
                bb[n][1] = *(const u32*)(wh + 16);
            }
            #pragma unroll
            for (int n = 0; n < 4; n++)
                #pragma unroll
                for (int m = 0; m < 2; m++)
                    mma16816(D3[m][n], ah3[m][kt], bb[n][0], bb[n][1]);
            #pragma unroll
            for (int n = 0; n < 4; n++)
                #pragma unroll
                for (int m = 0; m < 2; m++)
                    mma16816(D3[m][n], al3[m][kt], bb[n][0], bb[n][1]);
            #pragma unroll
            for (int n = 0; n < 4; n++) {
                const char* wl = sm + O_W3L + (8 * n + g) * S2 + kt * 32 + t * 4;
                bb[n][0] = *(const u32*)wl;
                bb[n][1] = *(const u32*)(wl + 16);
            }
            #pragma unroll
            for (int n = 0; n < 4; n++)
                #pragma unroll
                for (int m = 0; m < 2; m++)
                    mma16816(D3[m][n], ah3[m][kt], bb[n][0], bb[n][1]);
        }

        // ---- epilogue 3: relu(D3).W4 per row, cross-t reduce ----
        float S00 = 0.f, S01 = 0.f, S10 = 0.f, S11 = 0.f;
        #pragma unroll
        for (int nt = 0; nt < 4; nt++) {
            const float2 w4p = *(const float2*)(sW4f + nt * 8 + 2 * t);
            S00 += fmaxf(D3[0][nt][0], 0.f) * w4p.x + fmaxf(D3[0][nt][1], 0.f) * w4p.y;
            S01 += fmaxf(D3[0][nt][2], 0.f) * w4p.x + fmaxf(D3[0][nt][3], 0.f) * w4p.y;
            S10 += fmaxf(D3[1][nt][0], 0.f) * w4p.x + fmaxf(D3[1][nt][1], 0.f) * w4p.y;
            S11 += fmaxf(D3[1][nt][2], 0.f) * w4p.x + fmaxf(D3[1][nt][3], 0.f) * w4p.y;
        }
        #pragma unroll
        for (int off = 1; off <= 2; off <<= 1) {
            S00 += __shfl_xor_sync(0xffffffffu, S00, off);
            S01 += __shfl_xor_sync(0xffffffffu, S01, off);
            S10 += __shfl_xor_sync(0xffffffffu, S10, off);
            S11 += __shfl_xor_sync(0xffffffffu, S11, off);
        }
        __syncwarp();
        if (t == 0) {
            sSf[wid * 32 + g] = S00;
            sSf[wid * 32 + 8 + g] = S01;
            sSf[wid * 32 + 16 + g] = S10;
            sSf[wid * 32 + 24 + g] = S11;
        }
        __syncwarp();

        if (act) {
            const float s = sSf[wid * 32 + lane] + b4s;
            const float inv = 1.0f / (d + 1e-12f);
            const float cx = s * rx * inv;
            const float cy = s * ry * inv;
            const float cz = s * rz * inv;
            if (qs == 0) { wx0 += cx; wy0 += cy; wz0 += cz; }
            if (qs == 1) { wx1 += cx; wy1 += cy; wz1 += cz; }
            if (qs == 2) { wx2 += cx; wy2 += cy; wz2 += cz; }
            if (qs == 3) { wx3 += cx; wy3 += cy; wz3 += cz; }
        }
        __syncwarp();
    }

    __syncthreads();

    // ---- per-query reduction + final MLP 3->64->3 ----
    for (int qq = 0; qq < QPB; qq++) {
        const int q = blockIdx.x * QPB + qq;

        float X = (qq == 0) ? wx0 : (qq == 1) ? wx1 : (qq == 2) ? wx2 : wx3;
        float Y = (qq == 0) ? wy0 : (qq == 1) ? wy1 : (qq == 2) ? wy2 : wy3;
        float Z = (qq == 0) ? wz0 : (qq == 1) ? wz1 : (qq == 2) ? wz2 : wz3;

        #pragma unroll
        for (int o = 16; o > 0; o >>= 1) {
            X += __shfl_down_sync(0xffffffffu, X, o);
            Y += __shfl_down_sync(0xffffffffu, Y, o);
            Z += __shfl_down_sync(0xffffffffu, Z, o);
        }
        if (lane == 0) {
            sRed[wid * 3 + 0] = X;
            sRed[wid * 3 + 1] = Y;
            sRed[wid * 3 + 2] = Z;
        }
        __syncthreads();
        if (tid == 0) {
            float Xs = 0, Ys = 0, Zs = 0;
            #pragma unroll
            for (int w = 0; w < 4; w++) {
                Xs += sRed[w * 3 + 0];
                Ys += sRed[w * 3 + 1];
                Zs += sRed[w * 3 + 2];
            }
            sWgt[0] = Xs; sWgt[1] = Ys; sWgt[2] = Zs;
        }
        __syncthreads();

        float p0 = 0.0f, p1 = 0.0f, p2 = 0.0f;
        if (tid < 64) {
            const float Xs = sWgt[0], Ys = sWgt[1], Zs = sWgt[2];
            float hq = Xs * sW5[tid] + Ys * sW5[64 + tid] + Zs * sW5[128 + tid] + sb5[tid];
            hq = fmaxf(hq, 0.0f);
            p0 = hq * sW6[tid * 3 + 0];
            p1 = hq * sW6[tid * 3 + 1];
            p2 = hq * sW6[tid * 3 + 2];
        }
        #pragma unroll
        for (int o = 16; o > 0; o >>= 1) {
            p0 += __shfl_down_sync(0xffffffffu, p0, o);
            p1 += __shfl_down_sync(0xffffffffu, p1, o);
            p2 += __shfl_down_sync(0xffffffffu, p2, o);
        }
        if (tid == 0)  { sOut[0] = p0; sOut[1] = p1; sOut[2] = p2; }
        if (tid == 32) { sOut[3] = p0; sOut[4] = p1; sOut[5] = p2; }
        __syncthreads();
        if (tid == 0 && q < NQ) {
            out[q * 3 + 0] = sOut[0] + sOut[3] + b6[0];
            out[q * 3 + 1] = sOut[1] + sOut[4] + b6[1];
            out[q * 3 + 2] = sOut[2] + sOut[5] + b6[2];
        }
        __syncthreads();
    }
}

extern "C" void kernel_launch(void* const* d_in, const int* in_sizes, int n_in,
                              void* d_out, int out_size) {
    const float* apos  = (const float*)d_in[0];
    const float* afeat = (const float*)d_in[1];
    const float* qpos  = (const float*)d_in[2];
    const float* W1 = (const float*)d_in[3];
    const float* b1 = (const float*)d_in[4];
    const float* W2 = (const float*)d_in[5];
    const float* b2 = (const float*)d_in[6];
    const float* W3 = (const float*)d_in[7];
    const float* b3 = (const float*)d_in[8];
    const float* W4 = (const float*)d_in[9];
    const float* b4 = (const float*)d_in[10];
    const float* W5 = (const float*)d_in[11];
    const float* b5 = (const float*)d_in[12];
    const float* W6 = (const float*)d_in[13];
    const float* b6 = (const float*)d_in[14];
    float* out = (float*)d_out;

    const int NA = in_sizes[0] / 3;
    const int NQ = in_sizes[2] / 3;

    cudaFuncSetAttribute(fieldnet_mma_kernel,
                         cudaFuncAttributeMaxDynamicSharedMemorySize, DYN_SMEM);

    const int grid = (NQ + QPB - 1) / QPB;
    fieldnet_mma_kernel<<<grid, TPB, DYN_SMEM>>>(apos, afeat, qpos,
                                                 W1, b1, W2, b2, W3, b3, W4, b4,
                                                 W5, b5, W6, b6,
                                                 out, NA, NQ);
}